// round 11
// baseline (speedup 1.0000x reference)
#include <cuda_runtime.h>
#include <cuda_fp16.h>
#include <math.h>
#include <stdint.h>

#define EMBED    256
#define HEADS    8
#define LEVELS   4
#define POINTS   4
#define HEAD_DIM 32
#define NQ       20000
#define NB       2
#define HP       128
#define WP       128
#define NVAL     (NB*HP*WP*LEVELS)   // 131072
#define KDIM     256

// ---------------- device scratch (static, no allocations) ----------------
__device__ __half g_xn16[NQ*EMBED];                 // LN output fp16
__device__ float  g_ofat[NQ*384];                   // [off(256) | attn(128)]
__device__ __half g_fm16[(size_t)NVAL*EMBED];       // fmaps fp16
__device__ __half g_val [(size_t)NVAL*EMBED];       // projected value fp16
__device__ __half g_sm16[NQ*EMBED];                 // sampled output fp16
__device__ float  g_wqt [65536];                    // Wq transposed fp32
__device__ __half g_wc16[384*256];                  // W_comb fp16 K-major
__device__ __half g_wo16[65536];                    // W_out fp16 K-major
__device__ __half g_wv16[65536];                    // W_val fp16 K-major
__device__ float  g_bofat[384];

// ---------------- helpers ----------------
__device__ __forceinline__ uint32_t smem_u32(const void* p) {
    uint32_t a;
    asm("{ .reg .u64 t; cvta.to.shared.u64 t, %1; cvt.u32.u64 %0, t; }" : "=r"(a) : "l"(p));
    return a;
}
__device__ __forceinline__ void ldm_x4(uint32_t* r, uint32_t addr) {
    asm volatile("ldmatrix.sync.aligned.m8n8.x4.shared.b16 {%0,%1,%2,%3}, [%4];"
                 : "=r"(r[0]), "=r"(r[1]), "=r"(r[2]), "=r"(r[3]) : "r"(addr));
}
__device__ __forceinline__ void mma_f16(float* c, const uint32_t* a, const uint32_t* b) {
    asm volatile("mma.sync.aligned.m16n8k16.row.col.f32.f16.f16.f32 "
                 "{%0,%1,%2,%3},{%4,%5,%6,%7},{%8,%9},{%0,%1,%2,%3};"
                 : "+f"(c[0]), "+f"(c[1]), "+f"(c[2]), "+f"(c[3])
                 : "r"(a[0]), "r"(a[1]), "r"(a[2]), "r"(a[3]), "r"(b[0]), "r"(b[1]));
}
__device__ __forceinline__ void cp16(uint32_t dst, const void* src, bool pred) {
    size_t g = __cvta_generic_to_global(src);
    int sz = pred ? 16 : 0;
    asm volatile("cp.async.cg.shared.global [%0], [%1], 16, %2;"
                 :: "r"(dst), "l"(g), "r"(sz) : "memory");
}
#define CP_COMMIT() asm volatile("cp.async.commit_group;" ::: "memory")
#define CP_WAIT0()  asm volatile("cp.async.wait_group 0;" ::: "memory")

// ---------------- fp32 transpose ----------------
__global__ void transpose_f32(const float* __restrict__ src, float* __restrict__ dst)
{
    __shared__ float t[32][33];
    int bx = blockIdx.x * 32;
    int by = blockIdx.y * 32;
#pragma unroll
    for (int i = 0; i < 4; i++)
        t[threadIdx.y + i*8][threadIdx.x] = src[(size_t)(by + threadIdx.y + i*8)*256 + bx + threadIdx.x];
    __syncthreads();
#pragma unroll
    for (int i = 0; i < 4; i++)
        dst[(size_t)(bx + threadIdx.y + i*8)*256 + by + threadIdx.x] = t[threadIdx.x][threadIdx.y + i*8];
}

// ---------------- W_comb = Wq @ [W_off|W_attn] -> fp16 K-major ----------------
__global__ __launch_bounds__(256)
void wcomb_kernel(const float* __restrict__ Woff, const float* __restrict__ Wattn)
{
    __shared__ float col[4][256];
    const int j = threadIdx.x;
    const int n0 = blockIdx.x * 4;
#pragma unroll
    for (int i = 0; i < 4; i++) {
        int n = n0 + i;
        col[i][j] = (n < 256) ? Woff[j*256 + n] : Wattn[j*128 + (n - 256)];
    }
    __syncthreads();
    float a0 = 0.f, a1 = 0.f, a2 = 0.f, a3 = 0.f;
#pragma unroll 4
    for (int m = 0; m < 256; m++) {
        float w = g_wqt[m*256 + j];
        a0 += w * col[0][m];
        a1 += w * col[1][m];
        a2 += w * col[2][m];
        a3 += w * col[3][m];
    }
    g_wc16[(n0+0)*256 + j] = __float2half(a0);
    g_wc16[(n0+1)*256 + j] = __float2half(a1);
    g_wc16[(n0+2)*256 + j] = __float2half(a2);
    g_wc16[(n0+3)*256 + j] = __float2half(a3);
}

// ---------------- transpose to fp16 ----------------
__global__ void transpose_f16(const float* __restrict__ src, __half* __restrict__ dst)
{
    __shared__ float t[32][33];
    int bx = blockIdx.x * 32;
    int by = blockIdx.y * 32;
#pragma unroll
    for (int i = 0; i < 4; i++) {
        int y = by + threadIdx.y + i*8;
        t[threadIdx.y + i*8][threadIdx.x] = src[(size_t)y*256 + bx + threadIdx.x];
    }
    __syncthreads();
#pragma unroll
    for (int i = 0; i < 4; i++) {
        int row = bx + threadIdx.y + i*8;
        dst[(size_t)row*256 + by + threadIdx.x] = __float2half(t[threadIdx.x][threadIdx.y + i*8]);
    }
}

__global__ void bias_concat(const float* __restrict__ b_off, const float* __restrict__ b_attn)
{
    int i = threadIdx.x + blockIdx.x*blockDim.x;
    if (i < 384) g_bofat[i] = (i < 256) ? b_off[i] : b_attn[i-256];
}

// ---------------- streaming fp32 -> fp16 convert (8 elems/thread) ----------------
__global__ __launch_bounds__(256)
void cvt16_kernel(const float* __restrict__ src, __half* __restrict__ dst, size_t n8)
{
    size_t i = blockIdx.x * (size_t)blockDim.x + threadIdx.x;
    if (i >= n8) return;
    float4 a = *(const float4*)(src + i*8);
    float4 b = *(const float4*)(src + i*8 + 4);
    __half2 h0 = __floats2half2_rn(a.x, a.y);
    __half2 h1 = __floats2half2_rn(a.z, a.w);
    __half2 h2 = __floats2half2_rn(b.x, b.y);
    __half2 h3 = __floats2half2_rn(b.z, b.w);
    uint4 o;
    o.x = *(uint32_t*)&h0; o.y = *(uint32_t*)&h1;
    o.z = *(uint32_t*)&h2; o.w = *(uint32_t*)&h3;
    *(uint4*)(dst + i*8) = o;
}

#define LDA 40
#define HARR 10240
#define HSTG (2*HARR)
// ---------------- single-term fp16 GEMM (all projections) ----------------
// OM: 0 = fp32 out, 1 = fp16 out
template<int OM>
__global__ __launch_bounds__(256, 2)
void h_gemm(const __half* __restrict__ A, const __half* __restrict__ Bt,
            const float* __restrict__ bias, const float* __restrict__ Cadd,
            float* __restrict__ Cf, __half* __restrict__ Ch,
            int M, int Nglob)
{
    extern __shared__ __align__(16) char smem[];
    const uint32_t sb = smem_u32(smem);

    const int tid  = threadIdx.x;
    const int wid  = tid >> 5;
    const int lane = tid & 31;
    const int warpM = wid & 1;
    const int warpN = wid >> 1;
    const int rowBase = blockIdx.y * 128;
    const int colBase = blockIdx.x * 128;

    const int cp_row = tid >> 2;
    const int cp_c8  = (tid & 3) * 8;

    float acc[4][4][4];
#pragma unroll
    for (int i = 0; i < 4; i++)
#pragma unroll
        for (int j = 0; j < 4; j++)
#pragma unroll
            for (int k = 0; k < 4; k++) acc[i][j][k] = 0.f;

    const int a_row_off = lane & 15;
    const int a_k_off   = (lane >> 4) * 8;
    const int b_row_off = (lane & 7) + ((lane >> 4) << 3);
    const int b_k_off   = ((lane >> 3) & 1) * 8;

    auto copy_chunk = [&](int c, int stage) {
        const uint32_t s0 = sb + stage*HSTG;
#pragma unroll
        for (int j = 0; j < 2; j++) {
            int row = cp_row + j*64;
            uint32_t so = (uint32_t)(row*LDA + cp_c8) * 2;
            int ga = rowBase + row;
            bool pa = (ga < M);
            cp16(s0 +        so, A  + (size_t)ga*KDIM            + c*32 + cp_c8, pa);
            cp16(s0 + HARR + so, Bt + (size_t)(colBase+row)*KDIM + c*32 + cp_c8, true);
        }
        CP_COMMIT();
    };

    copy_chunk(0, 0);
    CP_WAIT0();
    __syncthreads();

    for (int c = 0; c < KDIM/32; c++) {
        const int s = c & 1;
        if (c < KDIM/32 - 1) copy_chunk(c + 1, s ^ 1);

        const uint32_t aB = sb + s*HSTG;
        const uint32_t bB = aB + HARR;
#pragma unroll
        for (int ks = 0; ks < 2; ks++) {
            const int kb = ks * 16;
            uint32_t bh[2][4];
#pragma unroll
            for (int np = 0; np < 2; np++) {
                int row = warpN*32 + np*16 + b_row_off;
                ldm_x4(bh[np], bB + (uint32_t)(row*LDA + kb + b_k_off)*2);
            }
#pragma unroll
            for (int mt = 0; mt < 4; mt++) {
                uint32_t ah[4];
                int row = warpM*64 + mt*16 + a_row_off;
                ldm_x4(ah, aB + (uint32_t)(row*LDA + kb + a_k_off)*2);
#pragma unroll
                for (int nt = 0; nt < 4; nt++)
                    mma_f16(acc[mt][nt], ah, &bh[nt>>1][(nt&1)*2]);
            }
        }
        if (c < KDIM/32 - 1) {
            CP_WAIT0();
            __syncthreads();
        }
    }

    const int g   = lane >> 2;
    const int tig = lane & 3;
#pragma unroll
    for (int mt = 0; mt < 4; mt++) {
#pragma unroll
        for (int half = 0; half < 2; half++) {
            int r = rowBase + warpM*64 + mt*16 + g + half*8;
            if (r >= M) continue;
#pragma unroll
            for (int nt = 0; nt < 4; nt++) {
                int col = colBase + warpN*32 + nt*8 + tig*2;
                float vx = acc[mt][nt][half*2+0];
                float vy = acc[mt][nt][half*2+1];
                if (bias) { vx += bias[col]; vy += bias[col+1]; }
                if (Cadd) {
                    float2 rr = *(const float2*)(Cadd + (size_t)r*Nglob + col);
                    vx += rr.x; vy += rr.y;
                }
                if (OM == 0)
                    *(float2*)(Cf + (size_t)r*Nglob + col) = make_float2(vx, vy);
                else
                    *(__half2*)(Ch + (size_t)r*Nglob + col) = __floats2half2_rn(vx, vy);
            }
        }
    }
}

// ---------------- LayerNorm -> fp16 ----------------
__global__ void ln_kernel(const float* __restrict__ q,
                          const float* __restrict__ gamma,
                          const float* __restrict__ beta)
{
    int warp = (blockIdx.x * blockDim.x + threadIdx.x) >> 5;
    int lane = threadIdx.x & 31;
    if (warp >= NQ) return;
    const float* row = q + (size_t)warp * EMBED;
    float v[8];
    float sum = 0.f;
#pragma unroll
    for (int i = 0; i < 8; i++) { v[i] = row[lane + i*32]; sum += v[i]; }
#pragma unroll
    for (int o = 16; o; o >>= 1) sum += __shfl_xor_sync(0xffffffffu, sum, o);
    float mean = sum * (1.0f/EMBED);
    float var = 0.f;
#pragma unroll
    for (int i = 0; i < 8; i++) { float d = v[i]-mean; var += d*d; }
#pragma unroll
    for (int o = 16; o; o >>= 1) var += __shfl_xor_sync(0xffffffffu, var, o);
    var *= (1.0f/EMBED);
    float inv = rsqrtf(var + 1e-5f);
#pragma unroll
    for (int i = 0; i < 8; i++) {
        int c = lane + i*32;
        float y = (v[i]-mean)*inv*gamma[c] + beta[c];
        g_xn16[(size_t)warp*EMBED + c] = __float2half(y);
    }
}

// ---------------- sampling: 1 query/block, two-phase, 8B gathers ----------------
// Phase 1: threads 0..127 = 8h x 16p; compute softmax weight, bilinear weights,
//          4 masked-premultiplied weights + 4 row base indices (uint2 units) -> smem.
// Phase 2: warp = head; lane = corner(lane>>3) x chan8(lane&7); one LDG.64/point;
//          butterfly-reduce over corners at the end.
__global__ __launch_bounds__(256)
void sample_kernel(const float* __restrict__ pos,
                   const int*   __restrict__ boff,
                   const int*   __restrict__ lshapes)
{
    __shared__ int   sIdx[128*4];
    __shared__ float sW  [128*4];

    const int tid = threadIdx.x;
    const int q   = blockIdx.x;

    // ---------- phase 1 ----------
    if (tid < 128) {
        const int h = tid >> 4;
        const int p = tid & 15;
        const int l = p >> 2;
        const int b = (q >= boff[1]) ? 1 : 0;

        const float posy = pos[q*2+0];
        const float posx = pos[q*2+1];
        const int   Hl = lshapes[l*2+0];
        const int   Wl = lshapes[l*2+1];
        const float hf = (float)Hl, wf = (float)Wl;

        const float* base = g_ofat + (size_t)q*384;
        const float oy    = base[h*32 + p*2 + 0];
        const float ox    = base[h*32 + p*2 + 1];
        const float logit = base[256 + h*16 + p];

        float mx = logit;
#pragma unroll
        for (int o = 8; o; o >>= 1) mx = fmaxf(mx, __shfl_xor_sync(0xffffffffu, mx, o));
        float e = expf(logit - mx);
        float s = e;
#pragma unroll
        for (int o = 8; o; o >>= 1) s += __shfl_xor_sync(0xffffffffu, s, o);
        const float a = e / s;

        const float py = (posy + oy/hf)*hf - 0.5f;
        const float px = (posx + ox/wf)*wf - 0.5f;
        const float y0f = floorf(py), x0f = floorf(px);
        const float wy = py - y0f,    wx = px - x0f;
        const int y0 = (int)y0f, x0 = (int)x0f;

#pragma unroll
        for (int cc = 0; cc < 4; cc++) {
            int yi = y0 + (cc >> 1);
            int xi = x0 + (cc & 1);
            bool m = (yi >= 0) & (yi < Hl) & (xi >= 0) & (xi < Wl);
            int yc = min(max(yi, 0), HP-1);
            int xc = min(max(xi, 0), WP-1);
            int rowi = ((b*HP + yc)*WP + xc)*LEVELS + l;
            // uint2 units: row = rowi*64, head offset = h*8
            sIdx[tid*4 + cc] = rowi*64 + h*8;
            float ww = a * ((cc >> 1) ? wy : (1.f-wy)) * ((cc & 1) ? wx : (1.f-wx));
            sW[tid*4 + cc] = m ? ww : 0.f;
        }
    }
    __syncthreads();

    // ---------- phase 2 ----------
    const int wid  = tid >> 5;         // head 0..7
    const int lane = tid & 31;
    const int c    = lane >> 3;        // corner
    const int e    = lane & 7;         // 8-byte chunk within head (4 halves)

    const uint2* vb = (const uint2*)g_val;

    float4 acc = make_float4(0.f, 0.f, 0.f, 0.f);
#pragma unroll
    for (int p = 0; p < 16; p++) {
        int   id = sIdx[(wid*16 + p)*4 + c];
        float w  = sW  [(wid*16 + p)*4 + c];
        uint2 d  = __ldg(vb + id + e);
        __half2 h0 = *(__half2*)&d.x;
        __half2 h1 = *(__half2*)&d.y;
        float2 f0 = __half22float2(h0);
        float2 f1 = __half22float2(h1);
        acc.x += w * f0.x;
        acc.y += w * f0.y;
        acc.z += w * f1.x;
        acc.w += w * f1.y;
    }
    // reduce over 4 corner groups (lanes differing in bits 3,4)
#pragma unroll
    for (int o = 8; o <= 16; o <<= 1) {
        acc.x += __shfl_xor_sync(0xffffffffu, acc.x, o);
        acc.y += __shfl_xor_sync(0xffffffffu, acc.y, o);
        acc.z += __shfl_xor_sync(0xffffffffu, acc.z, o);
        acc.w += __shfl_xor_sync(0xffffffffu, acc.w, o);
    }
    if (c == 0) {
        __half2 o0 = __floats2half2_rn(acc.x, acc.y);
        __half2 o1 = __floats2half2_rn(acc.z, acc.w);
        uint2 o;
        o.x = *(uint32_t*)&o0;
        o.y = *(uint32_t*)&o1;
        ((uint2*)g_sm16)[(size_t)q*64 + wid*8 + e] = o;
    }
}

// ---------------- launcher ----------------
extern "C" void kernel_launch(void* const* d_in, const int* in_sizes, int n_in,
                              void* d_out, int out_size)
{
    const float* query   = (const float*)d_in[0];
    const float* qpos    = (const float*)d_in[1];
    const int*   qboff   = (const int*)  d_in[2];
    const float* fmaps   = (const float*)d_in[3];
    const int*   lshapes = (const int*)  d_in[4];
    const float* gamma   = (const float*)d_in[5];
    const float* beta    = (const float*)d_in[6];
    const float* W_q     = (const float*)d_in[7];
    const float* W_off   = (const float*)d_in[8];
    const float* b_off   = (const float*)d_in[9];
    const float* W_attn  = (const float*)d_in[10];
    const float* b_attn  = (const float*)d_in[11];
    const float* W_val   = (const float*)d_in[12];
    const float* b_val   = (const float*)d_in[13];
    const float* W_out   = (const float*)d_in[14];
    float* out = (float*)d_out;

    __half *xn16, *sm16, *wc16, *wo16, *wv16, *val, *fm16;
    float *ofat, *bofat, *wqt;
    cudaGetSymbolAddress((void**)&xn16, g_xn16);
    cudaGetSymbolAddress((void**)&ofat, g_ofat);
    cudaGetSymbolAddress((void**)&fm16, g_fm16);
    cudaGetSymbolAddress((void**)&val,  g_val);
    cudaGetSymbolAddress((void**)&sm16, g_sm16);
    cudaGetSymbolAddress((void**)&wqt,  g_wqt);
    cudaGetSymbolAddress((void**)&wc16, g_wc16);
    cudaGetSymbolAddress((void**)&wo16, g_wo16);
    cudaGetSymbolAddress((void**)&wv16, g_wv16);
    cudaGetSymbolAddress((void**)&bofat, g_bofat);

    const int SMEMH = 2*HSTG;  // 40960
    cudaFuncSetAttribute(h_gemm<0>, cudaFuncAttributeMaxDynamicSharedMemorySize, SMEMH);
    cudaFuncSetAttribute(h_gemm<1>, cudaFuncAttributeMaxDynamicSharedMemorySize, SMEMH);

    dim3 tblk(32, 8);
    const int MQT = (NQ + 127) / 128;  // 157

    // ---- fork a second stream for the value path ----
    cudaStream_t s2;
    cudaStreamCreateWithFlags(&s2, cudaStreamNonBlocking);
    cudaEvent_t evFork, evJoin;
    cudaEventCreateWithFlags(&evFork, cudaEventDisableTiming);
    cudaEventCreateWithFlags(&evJoin, cudaEventDisableTiming);

    cudaEventRecord(evFork, 0);
    cudaStreamWaitEvent(s2, evFork, 0);

    // launches 1-3 (stream 0): query-path setup
    ln_kernel<<<(NQ*32 + 255)/256, 256>>>(query, gamma, beta);
    transpose_f32<<<dim3(8, 8), tblk>>>(W_q, wqt);
    wcomb_kernel<<<96, 256>>>(W_off, W_attn);
    // launches 4-6 (s2): value path  (val h_gemm is the 6th launch -> ncu -s 5 -c 1)
    transpose_f16<<<dim3(8, 8), tblk, 0, s2>>>(W_val, wv16);
    {
        size_t n8 = (size_t)NVAL*EMBED/8;   // 4.19M
        cvt16_kernel<<<(unsigned)((n8 + 255)/256), 256, 0, s2>>>(fmaps, fm16, n8);
    }
    h_gemm<1><<<dim3(2, NVAL/128), 256, SMEMH, s2>>>(fm16, wv16, b_val, nullptr,
                                                     nullptr, val, NVAL, 256);
    cudaEventRecord(evJoin, s2);
    // remaining query path on stream 0
    bias_concat<<<2, 192>>>(b_off, b_attn);
    transpose_f16<<<dim3(8, 8), tblk>>>(W_out, wo16);
    h_gemm<0><<<dim3(3, MQT), 256, SMEMH>>>(xn16, wc16, bofat, nullptr, ofat, nullptr, NQ, 384);

    // join: sampling needs g_val and g_ofat
    cudaStreamWaitEvent(0, evJoin, 0);
    sample_kernel<<<NQ, 256>>>(qpos, qboff, lshapes);
    // out = samp @ W_out + residual
    h_gemm<0><<<dim3(2, MQT), 256, SMEMH>>>(sm16, wo16, nullptr, query, out, nullptr, NQ, 256);
}

// round 12
// speedup vs baseline: 1.1078x; 1.1078x over previous
#include <cuda_runtime.h>
#include <cuda_fp16.h>
#include <math.h>
#include <stdint.h>

#define EMBED    256
#define HEADS    8
#define LEVELS   4
#define POINTS   4
#define HEAD_DIM 32
#define NQ       20000
#define NB       2
#define HP       128
#define WP       128
#define NVAL     (NB*HP*WP*LEVELS)   // 131072
#define KDIM     256
#define QSPLIT   9984                // 78 tiles of 128

// ---------------- device scratch (static, no allocations) ----------------
__device__ __half g_xn16[NQ*EMBED];                 // LN output fp16
__device__ float  g_ofat[NQ*384];                   // [off(256) | attn(128)]
__device__ __half g_val [(size_t)NVAL*EMBED];       // projected value fp16
__device__ __half g_sm16[NQ*EMBED];                 // sampled output fp16
__device__ float  g_wqt [65536];                    // Wq transposed fp32
__device__ __half g_wc16[384*256];                  // W_comb fp16 K-major
__device__ __half g_wo16[65536];                    // W_out fp16 K-major
__device__ __half g_wv16[65536];                    // W_val fp16 K-major
__device__ float  g_bofat[384];

// ---------------- helpers ----------------
__device__ __forceinline__ uint32_t smem_u32(const void* p) {
    uint32_t a;
    asm("{ .reg .u64 t; cvta.to.shared.u64 t, %1; cvt.u32.u64 %0, t; }" : "=r"(a) : "l"(p));
    return a;
}
__device__ __forceinline__ void ldm_x4(uint32_t* r, uint32_t addr) {
    asm volatile("ldmatrix.sync.aligned.m8n8.x4.shared.b16 {%0,%1,%2,%3}, [%4];"
                 : "=r"(r[0]), "=r"(r[1]), "=r"(r[2]), "=r"(r[3]) : "r"(addr));
}
__device__ __forceinline__ void mma_f16(float* c, const uint32_t* a, const uint32_t* b) {
    asm volatile("mma.sync.aligned.m16n8k16.row.col.f32.f16.f16.f32 "
                 "{%0,%1,%2,%3},{%4,%5,%6,%7},{%8,%9},{%0,%1,%2,%3};"
                 : "+f"(c[0]), "+f"(c[1]), "+f"(c[2]), "+f"(c[3])
                 : "r"(a[0]), "r"(a[1]), "r"(a[2]), "r"(a[3]), "r"(b[0]), "r"(b[1]));
}
__device__ __forceinline__ void cp16(uint32_t dst, const void* src, bool pred) {
    size_t g = __cvta_generic_to_global(src);
    int sz = pred ? 16 : 0;
    asm volatile("cp.async.cg.shared.global [%0], [%1], 16, %2;"
                 :: "r"(dst), "l"(g), "r"(sz) : "memory");
}
#define CP_COMMIT() asm volatile("cp.async.commit_group;" ::: "memory")
#define CP_WAIT0()  asm volatile("cp.async.wait_group 0;" ::: "memory")

// ---------------- fp32 transpose ----------------
__global__ void transpose_f32(const float* __restrict__ src, float* __restrict__ dst)
{
    __shared__ float t[32][33];
    int bx = blockIdx.x * 32;
    int by = blockIdx.y * 32;
#pragma unroll
    for (int i = 0; i < 4; i++)
        t[threadIdx.y + i*8][threadIdx.x] = src[(size_t)(by + threadIdx.y + i*8)*256 + bx + threadIdx.x];
    __syncthreads();
#pragma unroll
    for (int i = 0; i < 4; i++)
        dst[(size_t)(bx + threadIdx.y + i*8)*256 + by + threadIdx.x] = t[threadIdx.x][threadIdx.y + i*8];
}

// ---------------- W_comb = Wq @ [W_off|W_attn] -> fp16 K-major ----------------
__global__ __launch_bounds__(256)
void wcomb_kernel(const float* __restrict__ Woff, const float* __restrict__ Wattn)
{
    __shared__ float col[4][256];
    const int j = threadIdx.x;
    const int n0 = blockIdx.x * 4;
#pragma unroll
    for (int i = 0; i < 4; i++) {
        int n = n0 + i;
        col[i][j] = (n < 256) ? Woff[j*256 + n] : Wattn[j*128 + (n - 256)];
    }
    __syncthreads();
    float a0 = 0.f, a1 = 0.f, a2 = 0.f, a3 = 0.f;
#pragma unroll 4
    for (int m = 0; m < 256; m++) {
        float w = g_wqt[m*256 + j];
        a0 += w * col[0][m];
        a1 += w * col[1][m];
        a2 += w * col[2][m];
        a3 += w * col[3][m];
    }
    g_wc16[(n0+0)*256 + j] = __float2half(a0);
    g_wc16[(n0+1)*256 + j] = __float2half(a1);
    g_wc16[(n0+2)*256 + j] = __float2half(a2);
    g_wc16[(n0+3)*256 + j] = __float2half(a3);
}

// ---------------- transpose to fp16 ----------------
__global__ void transpose_f16(const float* __restrict__ src, __half* __restrict__ dst)
{
    __shared__ float t[32][33];
    int bx = blockIdx.x * 32;
    int by = blockIdx.y * 32;
#pragma unroll
    for (int i = 0; i < 4; i++) {
        int y = by + threadIdx.y + i*8;
        t[threadIdx.y + i*8][threadIdx.x] = src[(size_t)y*256 + bx + threadIdx.x];
    }
    __syncthreads();
#pragma unroll
    for (int i = 0; i < 4; i++) {
        int row = bx + threadIdx.y + i*8;
        dst[(size_t)row*256 + by + threadIdx.x] = __float2half(t[threadIdx.x][threadIdx.y + i*8]);
    }
}

__global__ void bias_concat(const float* __restrict__ b_off, const float* __restrict__ b_attn)
{
    int i = threadIdx.x + blockIdx.x*blockDim.x;
    if (i < 384) g_bofat[i] = (i < 256) ? b_off[i] : b_attn[i-256];
}

#define LDA 40
// ---------------- fp16 value GEMM, register-staged fp32->fp16 convert ----------------
// smem: A16[2] @ 0, 10240 ; B[2] @ 20480, 30720  (total 40960)
__global__ __launch_bounds__(256, 2)
void val_gemm(const float* __restrict__ A, const __half* __restrict__ Bt,
              const float* __restrict__ bias, __half* __restrict__ C)
{
    extern __shared__ __align__(16) char sm[];
    const uint32_t sb = smem_u32(sm);

    const int tid  = threadIdx.x;
    const int wid  = tid >> 5;
    const int lane = tid & 31;
    const int warpM = wid & 1;
    const int warpN = wid >> 1;
    const int rowBase = blockIdx.y * 128;
    const int colBase = blockIdx.x * 128;

    float acc[4][4][4];
#pragma unroll
    for (int i = 0; i < 4; i++)
#pragma unroll
        for (int j = 0; j < 4; j++)
#pragma unroll
            for (int k = 0; k < 4; k++) acc[i][j][k] = 0.f;

    const int a_row_off = lane & 15;
    const int a_k_off   = (lane >> 4) * 8;
    const int b_row_off = (lane & 7) + ((lane >> 4) << 3);
    const int b_k_off   = ((lane >> 3) & 1) * 8;

    float4 f[4];
    auto load_regs = [&](int c) {
#pragma unroll
        for (int j = 0; j < 4; j++) {
            int id = j*256 + tid;
            int row = id >> 3, c4 = (id & 7) << 2;
            f[j] = *(const float4*)(A + (size_t)(rowBase + row)*KDIM + c*32 + c4);
        }
    };
    auto sts_cvt = [&](int st) {
#pragma unroll
        for (int j = 0; j < 4; j++) {
            int id = j*256 + tid;
            int row = id >> 3, c4 = (id & 7) << 2;
            __half2 p0 = __floats2half2_rn(f[j].x, f[j].y);
            __half2 p1 = __floats2half2_rn(f[j].z, f[j].w);
            *(uint2*)(sm + st*10240 + (uint32_t)(row*LDA + c4)*2) =
                make_uint2(*(uint32_t*)&p0, *(uint32_t*)&p1);
        }
    };
    auto copyB = [&](int c, int st) {
#pragma unroll
        for (int j = 0; j < 2; j++) {
            int id = j*256 + tid;
            int row = id >> 2, c8 = (id & 3) * 8;
            cp16(sb + 20480 + st*10240 + (uint32_t)(row*LDA + c8)*2,
                 Bt + (size_t)(colBase + row)*KDIM + c*32 + c8, true);
        }
        CP_COMMIT();
    };

    load_regs(0);
    copyB(0, 0);
    sts_cvt(0);
    CP_WAIT0();
    __syncthreads();

    for (int c = 0; c < KDIM/32; c++) {
        const int s = c & 1;
        if (c < KDIM/32 - 1) { load_regs(c+1); copyB(c+1, s^1); }

        const uint32_t aB = sb + s*10240;
        const uint32_t bB = sb + 20480 + s*10240;
#pragma unroll
        for (int ks = 0; ks < 2; ks++) {
            const int kb = ks * 16;
            uint32_t bh[2][4];
#pragma unroll
            for (int np = 0; np < 2; np++) {
                int row = warpN*32 + np*16 + b_row_off;
                ldm_x4(bh[np], bB + (uint32_t)(row*LDA + kb + b_k_off)*2);
            }
#pragma unroll
            for (int mt = 0; mt < 4; mt++) {
                uint32_t ah[4];
                int row = warpM*64 + mt*16 + a_row_off;
                ldm_x4(ah, aB + (uint32_t)(row*LDA + kb + a_k_off)*2);
#pragma unroll
                for (int nt = 0; nt < 4; nt++)
                    mma_f16(acc[mt][nt], ah, &bh[nt>>1][(nt&1)*2]);
            }
        }
        if (c < KDIM/32 - 1) {
            __syncthreads();           // all warps finished MMA(c) (protects A16[s^1] write)
            sts_cvt(s^1);
            CP_WAIT0();
            __syncthreads();           // publish A16/B for chunk c+1
        }
    }

    const int g   = lane >> 2;
    const int tig = lane & 3;
#pragma unroll
    for (int mt = 0; mt < 4; mt++)
#pragma unroll
        for (int hf = 0; hf < 2; hf++) {
            int r = rowBase + warpM*64 + mt*16 + g + hf*8;
#pragma unroll
            for (int nt = 0; nt < 4; nt++) {
                int col = colBase + warpN*32 + nt*8 + tig*2;
                float vx = acc[mt][nt][hf*2+0] + bias[col];
                float vy = acc[mt][nt][hf*2+1] + bias[col+1];
                *(__half2*)(C + (size_t)r*256 + col) = __floats2half2_rn(vx, vy);
            }
        }
}

// ---------------- single-term fp16 GEMM (query-side) ----------------
#define HARR 10240
#define HSTG (2*HARR)
__global__ __launch_bounds__(256, 2)
void h_gemm(const __half* __restrict__ A, const __half* __restrict__ Bt,
            const float* __restrict__ bias, const float* __restrict__ Cadd,
            float* __restrict__ Cf, int M, int Nglob)
{
    extern __shared__ __align__(16) char smem[];
    const uint32_t sb = smem_u32(smem);

    const int tid  = threadIdx.x;
    const int wid  = tid >> 5;
    const int lane = tid & 31;
    const int warpM = wid & 1;
    const int warpN = wid >> 1;
    const int rowBase = blockIdx.y * 128;
    const int colBase = blockIdx.x * 128;

    const int cp_row = tid >> 2;
    const int cp_c8  = (tid & 3) * 8;

    float acc[4][4][4];
#pragma unroll
    for (int i = 0; i < 4; i++)
#pragma unroll
        for (int j = 0; j < 4; j++)
#pragma unroll
            for (int k = 0; k < 4; k++) acc[i][j][k] = 0.f;

    const int a_row_off = lane & 15;
    const int a_k_off   = (lane >> 4) * 8;
    const int b_row_off = (lane & 7) + ((lane >> 4) << 3);
    const int b_k_off   = ((lane >> 3) & 1) * 8;

    auto copy_chunk = [&](int c, int stage) {
        const uint32_t s0 = sb + stage*HSTG;
#pragma unroll
        for (int j = 0; j < 2; j++) {
            int row = cp_row + j*64;
            uint32_t so = (uint32_t)(row*LDA + cp_c8) * 2;
            int ga = rowBase + row;
            bool pa = (ga < M);
            cp16(s0 +        so, A  + (size_t)ga*KDIM            + c*32 + cp_c8, pa);
            cp16(s0 + HARR + so, Bt + (size_t)(colBase+row)*KDIM + c*32 + cp_c8, true);
        }
        CP_COMMIT();
    };

    copy_chunk(0, 0);
    CP_WAIT0();
    __syncthreads();

    for (int c = 0; c < KDIM/32; c++) {
        const int s = c & 1;
        if (c < KDIM/32 - 1) copy_chunk(c + 1, s ^ 1);

        const uint32_t aB = sb + s*HSTG;
        const uint32_t bB = aB + HARR;
#pragma unroll
        for (int ks = 0; ks < 2; ks++) {
            const int kb = ks * 16;
            uint32_t bh[2][4];
#pragma unroll
            for (int np = 0; np < 2; np++) {
                int row = warpN*32 + np*16 + b_row_off;
                ldm_x4(bh[np], bB + (uint32_t)(row*LDA + kb + b_k_off)*2);
            }
#pragma unroll
            for (int mt = 0; mt < 4; mt++) {
                uint32_t ah[4];
                int row = warpM*64 + mt*16 + a_row_off;
                ldm_x4(ah, aB + (uint32_t)(row*LDA + kb + a_k_off)*2);
#pragma unroll
                for (int nt = 0; nt < 4; nt++)
                    mma_f16(acc[mt][nt], ah, &bh[nt>>1][(nt&1)*2]);
            }
        }
        if (c < KDIM/32 - 1) {
            CP_WAIT0();
            __syncthreads();
        }
    }

    const int g   = lane >> 2;
    const int tig = lane & 3;
#pragma unroll
    for (int mt = 0; mt < 4; mt++) {
#pragma unroll
        for (int half = 0; half < 2; half++) {
            int r = rowBase + warpM*64 + mt*16 + g + half*8;
            if (r >= M) continue;
#pragma unroll
            for (int nt = 0; nt < 4; nt++) {
                int col = colBase + warpN*32 + nt*8 + tig*2;
                float vx = acc[mt][nt][half*2+0];
                float vy = acc[mt][nt][half*2+1];
                if (bias) { vx += bias[col]; vy += bias[col+1]; }
                if (Cadd) {
                    float2 rr = *(const float2*)(Cadd + (size_t)r*Nglob + col);
                    vx += rr.x; vy += rr.y;
                }
                *(float2*)(Cf + (size_t)r*Nglob + col) = make_float2(vx, vy);
            }
        }
    }
}

// ---------------- LayerNorm -> fp16 ----------------
__global__ void ln_kernel(const float* __restrict__ q,
                          const float* __restrict__ gamma,
                          const float* __restrict__ beta)
{
    int warp = (blockIdx.x * blockDim.x + threadIdx.x) >> 5;
    int lane = threadIdx.x & 31;
    if (warp >= NQ) return;
    const float* row = q + (size_t)warp * EMBED;
    float v[8];
    float sum = 0.f;
#pragma unroll
    for (int i = 0; i < 8; i++) { v[i] = row[lane + i*32]; sum += v[i]; }
#pragma unroll
    for (int o = 16; o; o >>= 1) sum += __shfl_xor_sync(0xffffffffu, sum, o);
    float mean = sum * (1.0f/EMBED);
    float var = 0.f;
#pragma unroll
    for (int i = 0; i < 8; i++) { float d = v[i]-mean; var += d*d; }
#pragma unroll
    for (int o = 16; o; o >>= 1) var += __shfl_xor_sync(0xffffffffu, var, o);
    var *= (1.0f/EMBED);
    float inv = rsqrtf(var + 1e-5f);
#pragma unroll
    for (int i = 0; i < 8; i++) {
        int c = lane + i*32;
        float y = (v[i]-mean)*inv*gamma[c] + beta[c];
        g_xn16[(size_t)warp*EMBED + c] = __float2half(y);
    }
}

// ---------------- sampling: 2 queries/block, two-phase (R10 structure) ----------------
__global__ __launch_bounds__(256)
void sample_kernel(const float* __restrict__ pos,
                   const int*   __restrict__ boff,
                   const int*   __restrict__ lshapes, int qbase)
{
    __shared__ int4   sIdx[256];
    __shared__ float4 sW  [256];

    const int tid = threadIdx.x;

    // ---------- phase 1 ----------
    {
        const int qq = qbase + blockIdx.x*2 + (tid >> 7);
        const int h  = (tid >> 4) & 7;
        const int p  = tid & 15;
        const int l  = p >> 2;
        const int b  = (qq >= boff[1]) ? 1 : 0;

        const float posy = pos[qq*2+0];
        const float posx = pos[qq*2+1];
        const int   Hl = lshapes[l*2+0];
        const int   Wl = lshapes[l*2+1];
        const float hf = (float)Hl, wf = (float)Wl;

        const float* base = g_ofat + (size_t)qq*384;
        const float oy    = base[h*32 + p*2 + 0];
        const float ox    = base[h*32 + p*2 + 1];
        const float logit = base[256 + h*16 + p];

        float mx = logit;
#pragma unroll
        for (int o = 8; o; o >>= 1) mx = fmaxf(mx, __shfl_xor_sync(0xffffffffu, mx, o));
        float e = expf(logit - mx);
        float s = e;
#pragma unroll
        for (int o = 8; o; o >>= 1) s += __shfl_xor_sync(0xffffffffu, s, o);
        const float a = e / s;

        const float py = (posy + oy/hf)*hf - 0.5f;
        const float px = (posx + ox/wf)*wf - 0.5f;
        const float y0f = floorf(py), x0f = floorf(px);
        const float wy = py - y0f,    wx = px - x0f;
        const int y0 = (int)y0f, x0 = (int)x0f;

        int   idx[4];
        float w[4];
#pragma unroll
        for (int cc = 0; cc < 4; cc++) {
            int yi = y0 + (cc >> 1);
            int xi = x0 + (cc & 1);
            bool m = (yi >= 0) & (yi < Hl) & (xi >= 0) & (xi < Wl);
            int yc = min(max(yi, 0), HP-1);
            int xc = min(max(xi, 0), WP-1);
            int rowi = ((b*HP + yc)*WP + xc)*LEVELS + l;
            idx[cc] = rowi*128 + h*16;   // half2 base (head folded in)
            float ww = a * ((cc >> 1) ? wy : (1.f-wy)) * ((cc & 1) ? wx : (1.f-wx));
            w[cc] = m ? ww : 0.f;
        }
        sIdx[tid] = make_int4(idx[0], idx[1], idx[2], idx[3]);
        sW[tid]   = make_float4(w[0], w[1], w[2], w[3]);
    }
    __syncthreads();

    // ---------- phase 2 ----------
    const int wid  = tid >> 5;
    const int lane = tid & 31;
    const int q    = qbase + blockIdx.x*2 + (wid >> 2);
    const int hb   = (wid & 3) * 2;
    const int ch   = lane & 15;
    const int hsel = lane >> 4;
    const int slotBase = ((wid >> 2) << 7) | ((hb + hsel) << 4);

    const __half2* vbase = (const __half2*)g_val;

    float2 acc = make_float2(0.f, 0.f);
#pragma unroll
    for (int p = 0; p < 16; p++) {
        int4   id = sIdx[slotBase + p];
        float4 w  = sW  [slotBase + p];
        float2 f0 = __half22float2(vbase[id.x + ch]);
        float2 f1 = __half22float2(vbase[id.y + ch]);
        float2 f2 = __half22float2(vbase[id.z + ch]);
        float2 f3 = __half22float2(vbase[id.w + ch]);
        acc.x += w.x*f0.x + w.y*f1.x + w.z*f2.x + w.w*f3.x;
        acc.y += w.x*f0.y + w.y*f1.y + w.z*f2.y + w.w*f3.y;
    }
    ((__half2*)g_sm16)[(size_t)q*128 + (hb + hsel)*16 + ch] = __floats2half2_rn(acc.x, acc.y);
}

// ---------------- launcher ----------------
extern "C" void kernel_launch(void* const* d_in, const int* in_sizes, int n_in,
                              void* d_out, int out_size)
{
    const float* query   = (const float*)d_in[0];
    const float* qpos    = (const float*)d_in[1];
    const int*   qboff   = (const int*)  d_in[2];
    const float* fmaps   = (const float*)d_in[3];
    const int*   lshapes = (const int*)  d_in[4];
    const float* gamma   = (const float*)d_in[5];
    const float* beta    = (const float*)d_in[6];
    const float* W_q     = (const float*)d_in[7];
    const float* W_off   = (const float*)d_in[8];
    const float* b_off   = (const float*)d_in[9];
    const float* W_attn  = (const float*)d_in[10];
    const float* b_attn  = (const float*)d_in[11];
    const float* W_val   = (const float*)d_in[12];
    const float* b_val   = (const float*)d_in[13];
    const float* W_out   = (const float*)d_in[14];
    float* out = (float*)d_out;

    __half *xn16, *sm16, *wc16, *wo16, *wv16, *val;
    float *ofat, *bofat, *wqt;
    cudaGetSymbolAddress((void**)&xn16, g_xn16);
    cudaGetSymbolAddress((void**)&ofat, g_ofat);
    cudaGetSymbolAddress((void**)&val,  g_val);
    cudaGetSymbolAddress((void**)&sm16, g_sm16);
    cudaGetSymbolAddress((void**)&wqt,  g_wqt);
    cudaGetSymbolAddress((void**)&wc16, g_wc16);
    cudaGetSymbolAddress((void**)&wo16, g_wo16);
    cudaGetSymbolAddress((void**)&wv16, g_wv16);
    cudaGetSymbolAddress((void**)&bofat, g_bofat);

    const int SMEMH = 2*HSTG;  // 40960
    const int SMEMV = 40960;
    cudaFuncSetAttribute(h_gemm,   cudaFuncAttributeMaxDynamicSharedMemorySize, SMEMH);
    cudaFuncSetAttribute(val_gemm, cudaFuncAttributeMaxDynamicSharedMemorySize, SMEMV);

    dim3 tblk(32, 8);
    const int MQT = (NQ + 127) / 128;  // 157

    // ---- fork a second stream for the value path ----
    cudaStream_t s2;
    cudaStreamCreateWithFlags(&s2, cudaStreamNonBlocking);
    cudaEvent_t evFork, evJoin, evS1, evOut;
    cudaEventCreateWithFlags(&evFork, cudaEventDisableTiming);
    cudaEventCreateWithFlags(&evJoin, cudaEventDisableTiming);
    cudaEventCreateWithFlags(&evS1,   cudaEventDisableTiming);
    cudaEventCreateWithFlags(&evOut,  cudaEventDisableTiming);

    cudaEventRecord(evFork, 0);
    cudaStreamWaitEvent(s2, evFork, 0);

    // value path on s2
    transpose_f16<<<dim3(8, 8), tblk, 0, s2>>>(W_val, wv16);
    val_gemm<<<dim3(2, NVAL/128), 256, SMEMV, s2>>>(fmaps, wv16, b_val, val);
    cudaEventRecord(evJoin, s2);

    // query path on stream 0
    ln_kernel<<<(NQ*32 + 255)/256, 256>>>(query, gamma, beta);
    transpose_f32<<<dim3(8, 8), tblk>>>(W_q, wqt);
    wcomb_kernel<<<96, 256>>>(W_off, W_attn);
    bias_concat<<<2, 192>>>(b_off, b_attn);
    transpose_f16<<<dim3(8, 8), tblk>>>(W_out, wo16);
    h_gemm<<<dim3(3, MQT), 256, SMEMH>>>(xn16, wc16, bofat, nullptr, ofat, NQ, 384);

    // join: sampling needs g_val and g_ofat
    cudaStreamWaitEvent(0, evJoin, 0);

    // ---- pipelined sample -> out across query halves ----
    // half 1: queries [0, QSPLIT)
    sample_kernel<<<QSPLIT/2, 256>>>(qpos, qboff, lshapes, 0);
    cudaEventRecord(evS1, 0);
    // half 2 sampling on stream 0
    sample_kernel<<<(NQ - QSPLIT)/2, 256>>>(qpos, qboff, lshapes, QSPLIT);
    // out GEMM for half 1 on s2, overlapping half-2 sampling
    cudaStreamWaitEvent(s2, evS1, 0);
    h_gemm<<<dim3(2, QSPLIT/128), 256, SMEMH, s2>>>(sm16, wo16, nullptr, query, out, QSPLIT, 256);
    cudaEventRecord(evOut, s2);
    // out GEMM for half 2 on stream 0
    h_gemm<<<dim3(2, (NQ - QSPLIT + 127)/128), 256, SMEMH>>>(
        sm16 + (size_t)QSPLIT*256, wo16, nullptr,
        query + (size_t)QSPLIT*256, out + (size_t)QSPLIT*256, NQ - QSPLIT, 256);
    // rejoin: graph end must include s2's out GEMM
    cudaStreamWaitEvent(0, evOut, 0);
}

// round 13
// speedup vs baseline: 1.1313x; 1.0213x over previous
#include <cuda_runtime.h>
#include <cuda_fp16.h>
#include <math.h>
#include <stdint.h>

#define EMBED    256
#define HEADS    8
#define LEVELS   4
#define POINTS   4
#define HEAD_DIM 32
#define NQ       20000
#define NB       2
#define HP       128
#define WP       128
#define NVAL     (NB*HP*WP*LEVELS)   // 131072
#define KDIM     256
#define QHALF    10000               // batch boundary (reference: [0,10000,20000])

// ---------------- device scratch (static, no allocations) ----------------
__device__ __half g_xn16[NQ*EMBED];                 // LN output fp16
__device__ float  g_ofat[NQ*384];                   // [off(256) | attn(128)]
__device__ __half g_val [(size_t)NVAL*EMBED];       // projected value fp16
__device__ __half g_sm16[NQ*EMBED];                 // sampled output fp16
__device__ float  g_wqt [65536];                    // Wq transposed fp32
__device__ __half g_wc16[384*256];                  // W_comb fp16 K-major
__device__ __half g_wo16[65536];                    // W_out fp16 K-major
__device__ __half g_wv16[65536];                    // W_val fp16 K-major
__device__ float  g_bofat[384];

// ---------------- helpers ----------------
__device__ __forceinline__ uint32_t smem_u32(const void* p) {
    uint32_t a;
    asm("{ .reg .u64 t; cvta.to.shared.u64 t, %1; cvt.u32.u64 %0, t; }" : "=r"(a) : "l"(p));
    return a;
}
__device__ __forceinline__ void ldm_x4(uint32_t* r, uint32_t addr) {
    asm volatile("ldmatrix.sync.aligned.m8n8.x4.shared.b16 {%0,%1,%2,%3}, [%4];"
                 : "=r"(r[0]), "=r"(r[1]), "=r"(r[2]), "=r"(r[3]) : "r"(addr));
}
__device__ __forceinline__ void mma_f16(float* c, const uint32_t* a, const uint32_t* b) {
    asm volatile("mma.sync.aligned.m16n8k16.row.col.f32.f16.f16.f32 "
                 "{%0,%1,%2,%3},{%4,%5,%6,%7},{%8,%9},{%0,%1,%2,%3};"
                 : "+f"(c[0]), "+f"(c[1]), "+f"(c[2]), "+f"(c[3])
                 : "r"(a[0]), "r"(a[1]), "r"(a[2]), "r"(a[3]), "r"(b[0]), "r"(b[1]));
}
__device__ __forceinline__ void cp16(uint32_t dst, const void* src, bool pred) {
    size_t g = __cvta_generic_to_global(src);
    int sz = pred ? 16 : 0;
    asm volatile("cp.async.cg.shared.global [%0], [%1], 16, %2;"
                 :: "r"(dst), "l"(g), "r"(sz) : "memory");
}
#define CP_COMMIT() asm volatile("cp.async.commit_group;" ::: "memory")
#define CP_WAIT0()  asm volatile("cp.async.wait_group 0;" ::: "memory")

// ---------------- fp32 transpose ----------------
__global__ void transpose_f32(const float* __restrict__ src, float* __restrict__ dst)
{
    __shared__ float t[32][33];
    int bx = blockIdx.x * 32;
    int by = blockIdx.y * 32;
#pragma unroll
    for (int i = 0; i < 4; i++)
        t[threadIdx.y + i*8][threadIdx.x] = src[(size_t)(by + threadIdx.y + i*8)*256 + bx + threadIdx.x];
    __syncthreads();
#pragma unroll
    for (int i = 0; i < 4; i++)
        dst[(size_t)(bx + threadIdx.y + i*8)*256 + by + threadIdx.x] = t[threadIdx.x][threadIdx.y + i*8];
}

// ---------------- W_comb = Wq @ [W_off|W_attn] -> fp16 K-major ----------------
__global__ __launch_bounds__(256)
void wcomb_kernel(const float* __restrict__ Woff, const float* __restrict__ Wattn)
{
    __shared__ float col[4][256];
    const int j = threadIdx.x;
    const int n0 = blockIdx.x * 4;
#pragma unroll
    for (int i = 0; i < 4; i++) {
        int n = n0 + i;
        col[i][j] = (n < 256) ? Woff[j*256 + n] : Wattn[j*128 + (n - 256)];
    }
    __syncthreads();
    float a0 = 0.f, a1 = 0.f, a2 = 0.f, a3 = 0.f;
#pragma unroll 4
    for (int m = 0; m < 256; m++) {
        float w = g_wqt[m*256 + j];
        a0 += w * col[0][m];
        a1 += w * col[1][m];
        a2 += w * col[2][m];
        a3 += w * col[3][m];
    }
    g_wc16[(n0+0)*256 + j] = __float2half(a0);
    g_wc16[(n0+1)*256 + j] = __float2half(a1);
    g_wc16[(n0+2)*256 + j] = __float2half(a2);
    g_wc16[(n0+3)*256 + j] = __float2half(a3);
}

// ---------------- transpose to fp16 ----------------
__global__ void transpose_f16(const float* __restrict__ src, __half* __restrict__ dst)
{
    __shared__ float t[32][33];
    int bx = blockIdx.x * 32;
    int by = blockIdx.y * 32;
#pragma unroll
    for (int i = 0; i < 4; i++) {
        int y = by + threadIdx.y + i*8;
        t[threadIdx.y + i*8][threadIdx.x] = src[(size_t)y*256 + bx + threadIdx.x];
    }
    __syncthreads();
#pragma unroll
    for (int i = 0; i < 4; i++) {
        int row = bx + threadIdx.y + i*8;
        dst[(size_t)row*256 + by + threadIdx.x] = __float2half(t[threadIdx.x][threadIdx.y + i*8]);
    }
}

__global__ void bias_concat(const float* __restrict__ b_off, const float* __restrict__ b_attn)
{
    int i = threadIdx.x + blockIdx.x*blockDim.x;
    if (i < 384) g_bofat[i] = (i < 256) ? b_off[i] : b_attn[i-256];
}

#define LDA 40
// ---------------- fp16 value GEMM, register-staged fp32->fp16 convert ----------------
__global__ __launch_bounds__(256, 2)
void val_gemm(const float* __restrict__ A, const __half* __restrict__ Bt,
              const float* __restrict__ bias, __half* __restrict__ C, int rowOff)
{
    extern __shared__ __align__(16) char sm[];
    const uint32_t sb = smem_u32(sm);

    const int tid  = threadIdx.x;
    const int wid  = tid >> 5;
    const int lane = tid & 31;
    const int warpM = wid & 1;
    const int warpN = wid >> 1;
    const int rowBase = rowOff + blockIdx.y * 128;
    const int colBase = blockIdx.x * 128;

    float acc[4][4][4];
#pragma unroll
    for (int i = 0; i < 4; i++)
#pragma unroll
        for (int j = 0; j < 4; j++)
#pragma unroll
            for (int k = 0; k < 4; k++) acc[i][j][k] = 0.f;

    const int a_row_off = lane & 15;
    const int a_k_off   = (lane >> 4) * 8;
    const int b_row_off = (lane & 7) + ((lane >> 4) << 3);
    const int b_k_off   = ((lane >> 3) & 1) * 8;

    float4 f[4];
    auto load_regs = [&](int c) {
#pragma unroll
        for (int j = 0; j < 4; j++) {
            int id = j*256 + tid;
            int row = id >> 3, c4 = (id & 7) << 2;
            f[j] = *(const float4*)(A + (size_t)(rowBase + row)*KDIM + c*32 + c4);
        }
    };
    auto sts_cvt = [&](int st) {
#pragma unroll
        for (int j = 0; j < 4; j++) {
            int id = j*256 + tid;
            int row = id >> 3, c4 = (id & 7) << 2;
            __half2 p0 = __floats2half2_rn(f[j].x, f[j].y);
            __half2 p1 = __floats2half2_rn(f[j].z, f[j].w);
            *(uint2*)(sm + st*10240 + (uint32_t)(row*LDA + c4)*2) =
                make_uint2(*(uint32_t*)&p0, *(uint32_t*)&p1);
        }
    };
    auto copyB = [&](int c, int st) {
#pragma unroll
        for (int j = 0; j < 2; j++) {
            int id = j*256 + tid;
            int row = id >> 2, c8 = (id & 3) * 8;
            cp16(sb + 20480 + st*10240 + (uint32_t)(row*LDA + c8)*2,
                 Bt + (size_t)(colBase + row)*KDIM + c*32 + c8, true);
        }
        CP_COMMIT();
    };

    load_regs(0);
    copyB(0, 0);
    sts_cvt(0);
    CP_WAIT0();
    __syncthreads();

    for (int c = 0; c < KDIM/32; c++) {
        const int s = c & 1;
        if (c < KDIM/32 - 1) { load_regs(c+1); copyB(c+1, s^1); }

        const uint32_t aB = sb + s*10240;
        const uint32_t bB = sb + 20480 + s*10240;
#pragma unroll
        for (int ks = 0; ks < 2; ks++) {
            const int kb = ks * 16;
            uint32_t bh[2][4];
#pragma unroll
            for (int np = 0; np < 2; np++) {
                int row = warpN*32 + np*16 + b_row_off;
                ldm_x4(bh[np], bB + (uint32_t)(row*LDA + kb + b_k_off)*2);
            }
#pragma unroll
            for (int mt = 0; mt < 4; mt++) {
                uint32_t ah[4];
                int row = warpM*64 + mt*16 + a_row_off;
                ldm_x4(ah, aB + (uint32_t)(row*LDA + kb + a_k_off)*2);
#pragma unroll
                for (int nt = 0; nt < 4; nt++)
                    mma_f16(acc[mt][nt], ah, &bh[nt>>1][(nt&1)*2]);
            }
        }
        if (c < KDIM/32 - 1) {
            __syncthreads();
            sts_cvt(s^1);
            CP_WAIT0();
            __syncthreads();
        }
    }

    const int g   = lane >> 2;
    const int tig = lane & 3;
#pragma unroll
    for (int mt = 0; mt < 4; mt++)
#pragma unroll
        for (int hf = 0; hf < 2; hf++) {
            int r = rowBase + warpM*64 + mt*16 + g + hf*8;
#pragma unroll
            for (int nt = 0; nt < 4; nt++) {
                int col = colBase + warpN*32 + nt*8 + tig*2;
                float vx = acc[mt][nt][hf*2+0] + bias[col];
                float vy = acc[mt][nt][hf*2+1] + bias[col+1];
                *(__half2*)(C + (size_t)r*256 + col) = __floats2half2_rn(vx, vy);
            }
        }
}

// ---------------- single-term fp16 GEMM (query-side) ----------------
#define HARR 10240
#define HSTG (2*HARR)
__global__ __launch_bounds__(256, 2)
void h_gemm(const __half* __restrict__ A, const __half* __restrict__ Bt,
            const float* __restrict__ bias, const float* __restrict__ Cadd,
            float* __restrict__ Cf, int M, int Nglob)
{
    extern __shared__ __align__(16) char smem[];
    const uint32_t sb = smem_u32(smem);

    const int tid  = threadIdx.x;
    const int wid  = tid >> 5;
    const int lane = tid & 31;
    const int warpM = wid & 1;
    const int warpN = wid >> 1;
    const int rowBase = blockIdx.y * 128;
    const int colBase = blockIdx.x * 128;

    const int cp_row = tid >> 2;
    const int cp_c8  = (tid & 3) * 8;

    float acc[4][4][4];
#pragma unroll
    for (int i = 0; i < 4; i++)
#pragma unroll
        for (int j = 0; j < 4; j++)
#pragma unroll
            for (int k = 0; k < 4; k++) acc[i][j][k] = 0.f;

    const int a_row_off = lane & 15;
    const int a_k_off   = (lane >> 4) * 8;
    const int b_row_off = (lane & 7) + ((lane >> 4) << 3);
    const int b_k_off   = ((lane >> 3) & 1) * 8;

    auto copy_chunk = [&](int c, int stage) {
        const uint32_t s0 = sb + stage*HSTG;
#pragma unroll
        for (int j = 0; j < 2; j++) {
            int row = cp_row + j*64;
            uint32_t so = (uint32_t)(row*LDA + cp_c8) * 2;
            int ga = rowBase + row;
            bool pa = (ga < M);
            cp16(s0 +        so, A  + (size_t)ga*KDIM            + c*32 + cp_c8, pa);
            cp16(s0 + HARR + so, Bt + (size_t)(colBase+row)*KDIM + c*32 + cp_c8, true);
        }
        CP_COMMIT();
    };

    copy_chunk(0, 0);
    CP_WAIT0();
    __syncthreads();

    for (int c = 0; c < KDIM/32; c++) {
        const int s = c & 1;
        if (c < KDIM/32 - 1) copy_chunk(c + 1, s ^ 1);

        const uint32_t aB = sb + s*HSTG;
        const uint32_t bB = aB + HARR;
#pragma unroll
        for (int ks = 0; ks < 2; ks++) {
            const int kb = ks * 16;
            uint32_t bh[2][4];
#pragma unroll
            for (int np = 0; np < 2; np++) {
                int row = warpN*32 + np*16 + b_row_off;
                ldm_x4(bh[np], bB + (uint32_t)(row*LDA + kb + b_k_off)*2);
            }
#pragma unroll
            for (int mt = 0; mt < 4; mt++) {
                uint32_t ah[4];
                int row = warpM*64 + mt*16 + a_row_off;
                ldm_x4(ah, aB + (uint32_t)(row*LDA + kb + a_k_off)*2);
#pragma unroll
                for (int nt = 0; nt < 4; nt++)
                    mma_f16(acc[mt][nt], ah, &bh[nt>>1][(nt&1)*2]);
            }
        }
        if (c < KDIM/32 - 1) {
            CP_WAIT0();
            __syncthreads();
        }
    }

    const int g   = lane >> 2;
    const int tig = lane & 3;
#pragma unroll
    for (int mt = 0; mt < 4; mt++) {
#pragma unroll
        for (int half = 0; half < 2; half++) {
            int r = rowBase + warpM*64 + mt*16 + g + half*8;
            if (r >= M) continue;
#pragma unroll
            for (int nt = 0; nt < 4; nt++) {
                int col = colBase + warpN*32 + nt*8 + tig*2;
                float vx = acc[mt][nt][half*2+0];
                float vy = acc[mt][nt][half*2+1];
                if (bias) { vx += bias[col]; vy += bias[col+1]; }
                if (Cadd) {
                    float2 rr = *(const float2*)(Cadd + (size_t)r*Nglob + col);
                    vx += rr.x; vy += rr.y;
                }
                *(float2*)(Cf + (size_t)r*Nglob + col) = make_float2(vx, vy);
            }
        }
    }
}

// ---------------- LayerNorm -> fp16 ----------------
__global__ void ln_kernel(const float* __restrict__ q,
                          const float* __restrict__ gamma,
                          const float* __restrict__ beta)
{
    int warp = (blockIdx.x * blockDim.x + threadIdx.x) >> 5;
    int lane = threadIdx.x & 31;
    if (warp >= NQ) return;
    const float* row = q + (size_t)warp * EMBED;
    float v[8];
    float sum = 0.f;
#pragma unroll
    for (int i = 0; i < 8; i++) { v[i] = row[lane + i*32]; sum += v[i]; }
#pragma unroll
    for (int o = 16; o; o >>= 1) sum += __shfl_xor_sync(0xffffffffu, sum, o);
    float mean = sum * (1.0f/EMBED);
    float var = 0.f;
#pragma unroll
    for (int i = 0; i < 8; i++) { float d = v[i]-mean; var += d*d; }
#pragma unroll
    for (int o = 16; o; o >>= 1) var += __shfl_xor_sync(0xffffffffu, var, o);
    var *= (1.0f/EMBED);
    float inv = rsqrtf(var + 1e-5f);
#pragma unroll
    for (int i = 0; i < 8; i++) {
        int c = lane + i*32;
        float y = (v[i]-mean)*inv*gamma[c] + beta[c];
        g_xn16[(size_t)warp*EMBED + c] = __float2half(y);
    }
}

// ---------------- sampling: 2 queries/block, two-phase ----------------
__global__ __launch_bounds__(256)
void sample_kernel(const float* __restrict__ pos,
                   const int*   __restrict__ boff,
                   const int*   __restrict__ lshapes, int qbase)
{
    __shared__ int4   sIdx[256];
    __shared__ float4 sW  [256];

    const int tid = threadIdx.x;

    // ---------- phase 1 ----------
    {
        const int qq = qbase + blockIdx.x*2 + (tid >> 7);
        const int h  = (tid >> 4) & 7;
        const int p  = tid & 15;
        const int l  = p >> 2;
        const int b  = (qq >= boff[1]) ? 1 : 0;

        const float posy = pos[qq*2+0];
        const float posx = pos[qq*2+1];
        const int   Hl = lshapes[l*2+0];
        const int   Wl = lshapes[l*2+1];
        const float hf = (float)Hl, wf = (float)Wl;

        const float* base = g_ofat + (size_t)qq*384;
        const float oy    = base[h*32 + p*2 + 0];
        const float ox    = base[h*32 + p*2 + 1];
        const float logit = base[256 + h*16 + p];

        float mx = logit;
#pragma unroll
        for (int o = 8; o; o >>= 1) mx = fmaxf(mx, __shfl_xor_sync(0xffffffffu, mx, o));
        float e = expf(logit - mx);
        float s = e;
#pragma unroll
        for (int o = 8; o; o >>= 1) s += __shfl_xor_sync(0xffffffffu, s, o);
        const float a = e / s;

        const float py = (posy + oy/hf)*hf - 0.5f;
        const float px = (posx + ox/wf)*wf - 0.5f;
        const float y0f = floorf(py), x0f = floorf(px);
        const float wy = py - y0f,    wx = px - x0f;
        const int y0 = (int)y0f, x0 = (int)x0f;

        int   idx[4];
        float w[4];
#pragma unroll
        for (int cc = 0; cc < 4; cc++) {
            int yi = y0 + (cc >> 1);
            int xi = x0 + (cc & 1);
            bool m = (yi >= 0) & (yi < Hl) & (xi >= 0) & (xi < Wl);
            int yc = min(max(yi, 0), HP-1);
            int xc = min(max(xi, 0), WP-1);
            int rowi = ((b*HP + yc)*WP + xc)*LEVELS + l;
            idx[cc] = rowi*128 + h*16;
            float ww = a * ((cc >> 1) ? wy : (1.f-wy)) * ((cc & 1) ? wx : (1.f-wx));
            w[cc] = m ? ww : 0.f;
        }
        sIdx[tid] = make_int4(idx[0], idx[1], idx[2], idx[3]);
        sW[tid]   = make_float4(w[0], w[1], w[2], w[3]);
    }
    __syncthreads();

    // ---------- phase 2 ----------
    const int wid  = tid >> 5;
    const int lane = tid & 31;
    const int q    = qbase + blockIdx.x*2 + (wid >> 2);
    const int hb   = (wid & 3) * 2;
    const int ch   = lane & 15;
    const int hsel = lane >> 4;
    const int slotBase = ((wid >> 2) << 7) | ((hb + hsel) << 4);

    const __half2* vbase = (const __half2*)g_val;

    float2 acc = make_float2(0.f, 0.f);
#pragma unroll
    for (int p = 0; p < 16; p++) {
        int4   id = sIdx[slotBase + p];
        float4 w  = sW  [slotBase + p];
        float2 f0 = __half22float2(vbase[id.x + ch]);
        float2 f1 = __half22float2(vbase[id.y + ch]);
        float2 f2 = __half22float2(vbase[id.z + ch]);
        float2 f3 = __half22float2(vbase[id.w + ch]);
        acc.x += w.x*f0.x + w.y*f1.x + w.z*f2.x + w.w*f3.x;
        acc.y += w.x*f0.y + w.y*f1.y + w.z*f2.y + w.w*f3.y;
    }
    ((__half2*)g_sm16)[(size_t)q*128 + (hb + hsel)*16 + ch] = __floats2half2_rn(acc.x, acc.y);
}

// ---------------- launcher ----------------
extern "C" void kernel_launch(void* const* d_in, const int* in_sizes, int n_in,
                              void* d_out, int out_size)
{
    const float* query   = (const float*)d_in[0];
    const float* qpos    = (const float*)d_in[1];
    const int*   qboff   = (const int*)  d_in[2];
    const float* fmaps   = (const float*)d_in[3];
    const int*   lshapes = (const int*)  d_in[4];
    const float* gamma   = (const float*)d_in[5];
    const float* beta    = (const float*)d_in[6];
    const float* W_q     = (const float*)d_in[7];
    const float* W_off   = (const float*)d_in[8];
    const float* b_off   = (const float*)d_in[9];
    const float* W_attn  = (const float*)d_in[10];
    const float* b_attn  = (const float*)d_in[11];
    const float* W_val   = (const float*)d_in[12];
    const float* b_val   = (const float*)d_in[13];
    const float* W_out   = (const float*)d_in[14];
    float* out = (float*)d_out;

    __half *xn16, *sm16, *wc16, *wo16, *wv16, *val;
    float *ofat, *bofat, *wqt;
    cudaGetSymbolAddress((void**)&xn16, g_xn16);
    cudaGetSymbolAddress((void**)&ofat, g_ofat);
    cudaGetSymbolAddress((void**)&val,  g_val);
    cudaGetSymbolAddress((void**)&sm16, g_sm16);
    cudaGetSymbolAddress((void**)&wqt,  g_wqt);
    cudaGetSymbolAddress((void**)&wc16, g_wc16);
    cudaGetSymbolAddress((void**)&wo16, g_wo16);
    cudaGetSymbolAddress((void**)&wv16, g_wv16);
    cudaGetSymbolAddress((void**)&bofat, g_bofat);

    const int SMEMH = 2*HSTG;  // 40960
    const int SMEMV = 40960;
    cudaFuncSetAttribute(h_gemm,   cudaFuncAttributeMaxDynamicSharedMemorySize, SMEMH);
    cudaFuncSetAttribute(val_gemm, cudaFuncAttributeMaxDynamicSharedMemorySize, SMEMV);

    dim3 tblk(32, 8);
    const int MQT = (NQ + 127) / 128;  // 157

    cudaStream_t s2;
    cudaStreamCreateWithFlags(&s2, cudaStreamNonBlocking);
    cudaEvent_t evFork, evV0, evV1, evS0, evOut;
    cudaEventCreateWithFlags(&evFork, cudaEventDisableTiming);
    cudaEventCreateWithFlags(&evV0,   cudaEventDisableTiming);
    cudaEventCreateWithFlags(&evV1,   cudaEventDisableTiming);
    cudaEventCreateWithFlags(&evS0,   cudaEventDisableTiming);
    cudaEventCreateWithFlags(&evOut,  cudaEventDisableTiming);

    cudaEventRecord(evFork, 0);
    cudaStreamWaitEvent(s2, evFork, 0);

    // ---- value path on s2, split by batch ----
    transpose_f16<<<dim3(8, 8), tblk, 0, s2>>>(W_val, wv16);
    val_gemm<<<dim3(2, (NVAL/2)/128), 256, SMEMV, s2>>>(fmaps, wv16, b_val, val, 0);
    cudaEventRecord(evV0, s2);
    val_gemm<<<dim3(2, (NVAL/2)/128), 256, SMEMV, s2>>>(fmaps, wv16, b_val, val, NVAL/2);
    cudaEventRecord(evV1, s2);

    // ---- query path on stream 0 ----
    ln_kernel<<<(NQ*32 + 255)/256, 256>>>(query, gamma, beta);
    transpose_f32<<<dim3(8, 8), tblk>>>(W_q, wqt);
    wcomb_kernel<<<96, 256>>>(W_off, W_attn);
    bias_concat<<<2, 192>>>(b_off, b_attn);
    transpose_f16<<<dim3(8, 8), tblk>>>(W_out, wo16);
    h_gemm<<<dim3(3, MQT), 256, SMEMH>>>(xn16, wc16, bofat, nullptr, ofat, NQ, 384);

    // ---- batch-0 sampling (needs val rows [0, NVAL/2) only) ----
    cudaStreamWaitEvent(0, evV0, 0);
    sample_kernel<<<QHALF/2, 256>>>(qpos, qboff, lshapes, 0);
    cudaEventRecord(evS0, 0);

    // ---- batch-1 sampling (needs full val) ----
    cudaStreamWaitEvent(0, evV1, 0);
    sample_kernel<<<(NQ - QHALF)/2, 256>>>(qpos, qboff, lshapes, QHALF);

    // ---- out GEMM pipelined: batch-0 on s2 (after its sampling), batch-1 on stream 0 ----
    cudaStreamWaitEvent(s2, evS0, 0);
    h_gemm<<<dim3(2, (QHALF + 127)/128), 256, SMEMH, s2>>>(sm16, wo16, nullptr, query, out, QHALF, 256);
    cudaEventRecord(evOut, s2);
    h_gemm<<<dim3(2, (NQ - QHALF + 127)/128), 256, SMEMH>>>(
        sm16 + (size_t)QHALF*256, wo16, nullptr,
        query + (size_t)QHALF*256, out + (size_t)QHALF*256, NQ - QHALF, 256);
    cudaStreamWaitEvent(0, evOut, 0);
}